// round 3
// baseline (speedup 1.0000x reference)
#include <cuda_runtime.h>

// Problem constants
#define BATCH 8
#define HW    256
#define HW2   65536
#define CMID  64
#define C3    169
#define KF    13
#define HO    244
#define HO2   59536   // 244*244

// Scratch (device globals; no allocation in kernel_launch)
__device__ float g_h1[BATCH * CMID * HW2];   // conv1 out (relu)
__device__ float g_h2[BATCH * CMID * HW2];   // conv2 out (relu)
__device__ float g_w [BATCH * C3 * HO2];     // conv3 out, cropped to interior
__device__ float g_W2t[CMID * 9 * CMID];     // [(ci*9+uv)*64 + co]
__device__ float g_W3t[CMID * 9 * C3];       // [(ci*9+uv)*169 + co]

// ---------------------------------------------------------------------------
// K0: weight transposes so the shared-memory weight tiles load coalesced
// ---------------------------------------------------------------------------
__global__ void transpose_w2(const float* __restrict__ W2) {
    int idx = blockIdx.x * 256 + threadIdx.x;
    if (idx < CMID * CMID * 9) {
        int co = idx / 576;        // W2[co][ci][u][v]
        int r  = idx % 576;        // ci*9 + uv
        g_W2t[r * CMID + co] = W2[idx];
    }
}

__global__ void transpose_w3(const float* __restrict__ W3) {
    int idx = blockIdx.x * 256 + threadIdx.x;
    if (idx < C3 * CMID * 9) {
        int co = idx / 576;
        int r  = idx % 576;
        g_W3t[r * C3 + co] = W3[idx];
    }
}

// ---------------------------------------------------------------------------
// K1: conv1 (1 -> 64) + relu, SAME. Tile 32x8, 256 threads, 1 px/thread.
// ---------------------------------------------------------------------------
__global__ __launch_bounds__(256) void conv1_kernel(
    const float* __restrict__ x, const float* __restrict__ W1,
    const float* __restrict__ b1)
{
    __shared__ float sW[576];
    __shared__ float sB[64];
    __shared__ float sX[10][35];

    int b  = blockIdx.z;
    int x0 = blockIdx.x * 32;
    int y0 = blockIdx.y * 8;
    int tid = threadIdx.x;

    for (int e = tid; e < 576; e += 256) sW[e] = W1[e];
    if (tid < 64) sB[tid] = b1[tid];
    for (int e = tid; e < 340; e += 256) {
        int r = e / 34, cc = e % 34;
        int gr = y0 - 1 + r, gc = x0 - 1 + cc;
        float v = 0.f;
        if (gr >= 0 && gr < HW && gc >= 0 && gc < HW)
            v = x[b * HW2 + gr * HW + gc];
        sX[r][cc] = v;
    }
    __syncthreads();

    int tx = tid & 31, ty = tid >> 5;
    float xv[9];
#pragma unroll
    for (int u = 0; u < 3; u++)
#pragma unroll
        for (int v = 0; v < 3; v++) xv[u * 3 + v] = sX[ty + u][tx + v];

    int oidx = (b * CMID) * HW2 + (y0 + ty) * HW + (x0 + tx);
#pragma unroll 4
    for (int co = 0; co < CMID; co++) {
        float a = sB[co];
#pragma unroll
        for (int k = 0; k < 9; k++) a += xv[k] * sW[co * 9 + k];
        g_h1[oidx + co * HW2] = fmaxf(a, 0.f);
    }
}

// ---------------------------------------------------------------------------
// K2: conv2 (64 -> 64) + relu, SAME.
// Tile 32x8 px, 512 threads = 64 px-slots x 8 co-groups.
// Each thread: 4 horizontal px x 8 co (32 accumulators).
// ---------------------------------------------------------------------------
#define TW  32
#define TH  8
#define CIC 8

__global__ __launch_bounds__(512, 2) void conv2_kernel(const float* __restrict__ b2)
{
    __shared__ float sIn[CIC][TH + 2][TW + 3];
    __shared__ __align__(16) float sW[CIC][9][CMID];

    int b  = blockIdx.z;
    int x0 = blockIdx.x * TW;
    int y0 = blockIdx.y * TH;
    int tid  = threadIdx.x;
    int cg   = tid >> 6;       // 0..7 co-group
    int slot = tid & 63;
    int sy   = slot >> 3;      // 0..7 row
    int sx   = slot & 7;       // 0..7
    int px0  = sx * 4;
    int co0  = cg * 8;

    float bias[8];
#pragma unroll
    for (int c = 0; c < 8; c++) bias[c] = __ldg(&b2[co0 + c]);

    float acc[4][8];
#pragma unroll
    for (int k = 0; k < 4; k++)
#pragma unroll
        for (int c = 0; c < 8; c++) acc[k][c] = bias[c];

    for (int cic = 0; cic < CMID / CIC; cic++) {
        int ci0 = cic * CIC;
        __syncthreads();
        // input tile chunk (with SAME zero padding)
        for (int e = tid; e < CIC * (TH + 2) * 34; e += 512) {
            int ci  = e / ((TH + 2) * 34);
            int rem = e % ((TH + 2) * 34);
            int r = rem / 34, cc = rem % 34;
            int gr = y0 - 1 + r, gc = x0 - 1 + cc;
            float v = 0.f;
            if (gr >= 0 && gr < HW && gc >= 0 && gc < HW)
                v = g_h1[(b * CMID + ci0 + ci) * HW2 + gr * HW + gc];
            sIn[ci][r][cc] = v;
        }
        // weight chunk (coalesced from transposed layout)
        for (int e = tid; e < CIC * 9 * CMID; e += 512) {
            int co = e & 63;
            int rc = e >> 6;          // 0..71
            int ci = rc / 9, uv = rc % 9;
            sW[ci][uv][co] = g_W2t[((ci0 + ci) * 9 + uv) * CMID + co];
        }
        __syncthreads();

#pragma unroll
        for (int ci = 0; ci < CIC; ci++) {
#pragma unroll
            for (int u = 0; u < 3; u++) {
                float xr[6];
#pragma unroll
                for (int k = 0; k < 6; k++) xr[k] = sIn[ci][sy + u][px0 + k];
#pragma unroll
                for (int v = 0; v < 3; v++) {
                    const float4 wa = *(const float4*)&sW[ci][u * 3 + v][co0];
                    const float4 wb = *(const float4*)&sW[ci][u * 3 + v][co0 + 4];
#pragma unroll
                    for (int k = 0; k < 4; k++) {
                        float xv = xr[k + v];
                        acc[k][0] += xv * wa.x; acc[k][1] += xv * wa.y;
                        acc[k][2] += xv * wa.z; acc[k][3] += xv * wa.w;
                        acc[k][4] += xv * wb.x; acc[k][5] += xv * wb.y;
                        acc[k][6] += xv * wb.z; acc[k][7] += xv * wb.w;
                    }
                }
            }
        }
    }

#pragma unroll
    for (int c = 0; c < 8; c++) {
        float4 o;
        o.x = fmaxf(acc[0][c], 0.f);
        o.y = fmaxf(acc[1][c], 0.f);
        o.z = fmaxf(acc[2][c], 0.f);
        o.w = fmaxf(acc[3][c], 0.f);
        *(float4*)&g_h2[(b * CMID + co0 + c) * HW2 + (y0 + sy) * HW + x0 + px0] = o;
    }
}

// ---------------------------------------------------------------------------
// K3: conv3 (64 -> 169), evaluated ONLY on the cropped interior:
// output index (i,j) in [0,244)^2 corresponds to conv3 at (i+6, j+6).
// Same blocking as K2; loops 3 co-chunks of 64 (last partial, 169).
// ---------------------------------------------------------------------------
__global__ __launch_bounds__(512, 2) void conv3_kernel(const float* __restrict__ b3)
{
    __shared__ float sIn[CIC][TH + 2][TW + 3];
    __shared__ __align__(16) float sW[CIC][9][CMID];

    int b  = blockIdx.z;
    int j0 = blockIdx.x * TW;
    int i0 = blockIdx.y * TH;
    int tid  = threadIdx.x;
    int cg   = tid >> 6;
    int slot = tid & 63;
    int sy   = slot >> 3;
    int sx   = slot & 7;
    int px0  = sx * 4;
    int co0  = cg * 8;

    for (int coit = 0; coit < 3; coit++) {
        int cobase = coit * 64 + co0;

        float acc[4][8];
#pragma unroll
        for (int c = 0; c < 8; c++) {
            float bb = (cobase + c < C3) ? __ldg(&b3[cobase + c]) : 0.f;
#pragma unroll
            for (int k = 0; k < 4; k++) acc[k][c] = bb;
        }

        for (int cic = 0; cic < CMID / CIC; cic++) {
            int ci0 = cic * CIC;
            __syncthreads();
            // h2 tile: rows i0+5 .. i0+5+9, cols j0+5 .. (interior; only right edge can OOB)
            for (int e = tid; e < CIC * (TH + 2) * 34; e += 512) {
                int ci  = e / ((TH + 2) * 34);
                int rem = e % ((TH + 2) * 34);
                int r = rem / 34, cc = rem % 34;
                int gr = i0 + 5 + r, gc = j0 + 5 + cc;
                float v = 0.f;
                if (gr < HW && gc < HW)
                    v = g_h2[(b * CMID + ci0 + ci) * HW2 + gr * HW + gc];
                sIn[ci][r][cc] = v;
            }
            for (int e = tid; e < CIC * 9 * CMID; e += 512) {
                int co = e & 63;
                int rc = e >> 6;
                int ci = rc / 9, uv = rc % 9;
                int coglob = coit * 64 + co;
                sW[ci][uv][co] = (coglob < C3)
                    ? g_W3t[((ci0 + ci) * 9 + uv) * C3 + coglob] : 0.f;
            }
            __syncthreads();

#pragma unroll
            for (int ci = 0; ci < CIC; ci++) {
#pragma unroll
                for (int u = 0; u < 3; u++) {
                    float xr[6];
#pragma unroll
                    for (int k = 0; k < 6; k++) xr[k] = sIn[ci][sy + u][px0 + k];
#pragma unroll
                    for (int v = 0; v < 3; v++) {
                        const float4 wa = *(const float4*)&sW[ci][u * 3 + v][co0];
                        const float4 wb = *(const float4*)&sW[ci][u * 3 + v][co0 + 4];
#pragma unroll
                        for (int k = 0; k < 4; k++) {
                            float xv = xr[k + v];
                            acc[k][0] += xv * wa.x; acc[k][1] += xv * wa.y;
                            acc[k][2] += xv * wa.z; acc[k][3] += xv * wa.w;
                            acc[k][4] += xv * wb.x; acc[k][5] += xv * wb.y;
                            acc[k][6] += xv * wb.z; acc[k][7] += xv * wb.w;
                        }
                    }
                }
            }
        }

        int i = i0 + sy, j = j0 + px0;
        if (i < HO && j < HO) {   // j multiple of 4 and HO%4==0 -> full float4 or nothing
#pragma unroll
            for (int c = 0; c < 8; c++) {
                int co = cobase + c;
                if (co < C3) {
                    *(float4*)&g_w[((b * C3 + co) * HO + i) * HO + j] =
                        make_float4(acc[0][c], acc[1][c], acc[2][c], acc[3][c]);
                }
            }
        }
    }
}

// ---------------------------------------------------------------------------
// K4: NLM contraction: y[b,i,j] = sum_{u,v} w[b,u*13+v,i,j] * x[b,i+u,j+v]
// ---------------------------------------------------------------------------
__global__ __launch_bounds__(256) void nlm_kernel(
    const float* __restrict__ x, float* __restrict__ y)
{
    __shared__ float sX[20][44];
    int b  = blockIdx.z;
    int j0 = blockIdx.x * 32;
    int i0 = blockIdx.y * 8;
    int tid = threadIdx.x;

    for (int e = tid; e < 20 * 44; e += 256) {
        int r = e / 44, cc = e % 44;
        int gr = i0 + r, gc = j0 + cc;
        sX[r][cc] = (gr < HW && gc < HW) ? x[b * HW2 + gr * HW + gc] : 0.f;
    }
    __syncthreads();

    int tx = tid & 31, ty = tid >> 5;
    int i = i0 + ty, j = j0 + tx;
    if (i < HO && j < HO) {
        float a = 0.f;
        int wbase = (b * C3) * HO2 + i * HO + j;
#pragma unroll 1
        for (int u = 0; u < KF; u++) {
#pragma unroll
            for (int v = 0; v < KF; v++) {
                int c = u * KF + v;
                a += g_w[wbase + c * HO2] * sX[ty + u][tx + v];
            }
        }
        y[b * HO2 + i * HO + j] = a;
    }
}

// ---------------------------------------------------------------------------
extern "C" void kernel_launch(void* const* d_in, const int* in_sizes, int n_in,
                              void* d_out, int out_size)
{
    const float* x  = (const float*)d_in[0];
    const float* W1 = (const float*)d_in[1];
    const float* b1 = (const float*)d_in[2];
    const float* W2 = (const float*)d_in[3];
    const float* b2 = (const float*)d_in[4];
    const float* W3 = (const float*)d_in[5];
    const float* b3 = (const float*)d_in[6];
    float* y = (float*)d_out;

    transpose_w2<<<(CMID * CMID * 9 + 255) / 256, 256>>>(W2);
    transpose_w3<<<(C3 * CMID * 9 + 255) / 256, 256>>>(W3);
    conv1_kernel<<<dim3(HW / 32, HW / 8, BATCH), 256>>>(x, W1, b1);
    conv2_kernel<<<dim3(HW / TW, HW / TH, BATCH), 512>>>(b2);
    conv3_kernel<<<dim3((HO + TW - 1) / TW, (HO + TH - 1) / TH, BATCH), 512>>>(b3);
    nlm_kernel<<<dim3((HO + 31) / 32, (HO + 7) / 8, BATCH), 256>>>(x, y);
}